// round 5
// baseline (speedup 1.0000x reference)
#include <cuda_runtime.h>
#include <math.h>

#define EPSF 1e-8f
#define BB 64
#define NN 1024
#define WW 128

__device__ float g_sim[BB * NN];   // scratch: similarity logits

__device__ __forceinline__ float warp_sum(float v) {
#pragma unroll
    for (int o = 16; o; o >>= 1) v += __shfl_xor_sync(0xffffffffu, v, o);
    return v;
}
__device__ __forceinline__ float warp_max(float v) {
#pragma unroll
    for (int o = 16; o; o >>= 1) v = fmaxf(v, __shfl_xor_sync(0xffffffffu, v, o));
    return v;
}

// Phase 1: cosine similarity * beta + fused memory passthrough.
// R3 shape: 4 rows/warp, 8 warps/block, grid = B*N/32 = 2048 blocks, 32 regs.
// PDL: trigger after g_sim stores; the 32MB passthrough stores happen after,
// overlapping the dependent weights/link kernels.
__global__ __launch_bounds__(256) void wh_sim_kernel(
    const float* __restrict__ w_key, const float* __restrict__ w_beta,
    const float* __restrict__ memory, float* __restrict__ out_mem)
{
    const int t = threadIdx.x;
    const int lane = t & 31;
    const int warp = t >> 5;
    const size_t row0 = ((size_t)blockIdx.x * 8 + warp) * 4;  // first of 4 rows
    const int b = (int)(row0 >> 10);

    __shared__ float s_key[WW];
    if (t < WW) s_key[t] = w_key[b * WW + t];
    __syncthreads();

    float ks = 0.f;
#pragma unroll
    for (int i = lane; i < WW; i += 32) { float v = s_key[i]; ks += v * v; }
    ks = warp_sum(ks);
    const float knorm = sqrtf(ks) + EPSF;

    const float bx = w_beta[b];
    const float beta = 1.f + (bx > 20.f ? bx : log1pf(expf(bx)));
    const float4 k4 = reinterpret_cast<const float4*>(s_key)[lane];

    float4 m[4];
#pragma unroll
    for (int r = 0; r < 4; r++)
        m[r] = reinterpret_cast<const float4*>(memory + (row0 + r) * WW)[lane];

    float dot[4], sq[4];
#pragma unroll
    for (int r = 0; r < 4; r++) {
        dot[r] = m[r].x * k4.x + m[r].y * k4.y + m[r].z * k4.z + m[r].w * k4.w;
        sq[r]  = m[r].x * m[r].x + m[r].y * m[r].y + m[r].z * m[r].z + m[r].w * m[r].w;
    }
#pragma unroll
    for (int o = 16; o; o >>= 1) {
#pragma unroll
        for (int r = 0; r < 4; r++) {
            dot[r] += __shfl_xor_sync(0xffffffffu, dot[r], o);
            sq[r]  += __shfl_xor_sync(0xffffffffu, sq[r], o);
        }
    }
    if (lane == 0) {
#pragma unroll
        for (int r = 0; r < 4; r++)
            g_sim[row0 + r] = beta * dot[r] / ((sqrtf(sq[r]) + EPSF) * knorm);
    }

    // g_sim done for this block -> let dependents launch
#if __CUDA_ARCH__ >= 900
    cudaTriggerProgrammaticLaunchCompletion();
#endif

    // passthrough copy tail (overlaps dependent kernels)
#pragma unroll
    for (int r = 0; r < 4; r++)
        __stcs(reinterpret_cast<float4*>(out_mem + (row0 + r) * WW) + lane, m[r]);
}

// Phase 2: softmax over N, gated write weights, precedence. One block per batch.
__global__ __launch_bounds__(256) void wh_weights_kernel(
    const float* __restrict__ a_gate, const float* __restrict__ w_gate,
    const float* __restrict__ alloc, const float* __restrict__ prec,
    float* __restrict__ out_w, float* __restrict__ out_prec)
{
    const int b = blockIdx.x;
    const int t = threadIdx.x;
    const int lane = t & 31;
    const int warp = t >> 5;

    __shared__ float s_red[8];

    // prologue: independent inputs (before grid-dep sync)
    const float wg = 1.f / (1.f + expf(-w_gate[b]));
    const float ag = 1.f / (1.f + expf(-a_gate[b]));
    float av[4], pv[4];
#pragma unroll
    for (int r = 0; r < 4; r++) {
        av[r] = alloc[(size_t)b * NN + t + r * 256];
        pv[r] = prec[(size_t)b * NN + t + r * 256];
    }

#if __CUDA_ARCH__ >= 900
    cudaGridDependencySynchronize();
#endif

    float sv[4];
    float mx = -INFINITY;
#pragma unroll
    for (int r = 0; r < 4; r++) {
        sv[r] = g_sim[(size_t)b * NN + t + r * 256];
        mx = fmaxf(mx, sv[r]);
    }
    mx = warp_max(mx);
    if (lane == 0) s_red[warp] = mx;
    __syncthreads();
    mx = s_red[0];
#pragma unroll
    for (int i = 1; i < 8; i++) mx = fmaxf(mx, s_red[i]);

    float ev[4];
    float esum = 0.f;
#pragma unroll
    for (int r = 0; r < 4; r++) {
        float e = expf(sv[r] - mx);
        ev[r] = e;
        esum += e;
    }
    __syncthreads();
    esum = warp_sum(esum);
    if (lane == 0) s_red[warp] = esum;
    __syncthreads();
    float ssum = s_red[0];
#pragma unroll
    for (int i = 1; i < 8; i++) ssum += s_red[i];
    const float inv = 1.f / ssum;

    float wv[4];
    float wsum = 0.f;
#pragma unroll
    for (int r = 0; r < 4; r++) {
        const int n = t + r * 256;
        const float c = ev[r] * inv;
        const float w = wg * (ag * av[r] + (1.f - ag) * c);
        wv[r] = w;
        wsum += w;
        out_w[(size_t)b * NN + n] = w;
    }

    // out_w written by this block -> let link launch
#if __CUDA_ARCH__ >= 900
    cudaTriggerProgrammaticLaunchCompletion();
#endif

    __syncthreads();
    wsum = warp_sum(wsum);
    if (lane == 0) s_red[warp] = wsum;
    __syncthreads();
    float tot = s_red[0];
#pragma unroll
    for (int i = 1; i < 8; i++) tot += s_red[i];

#pragma unroll
    for (int r = 0; r < 4; r++) {
        const int n = t + r * 256;
        out_prec[(size_t)b * NN + n] = (1.f - tot) * pv[r] + wv[r];
    }
}

// Link update: 4 rows per block. Loads L and p BEFORE grid-dep sync (overlap),
// reads w only after. link = (1 - wi - wj)*L + wi*pj; diag = 0.
__global__ __launch_bounds__(256) void wh_link_kernel(
    const float* __restrict__ L, const float* __restrict__ w,
    const float* __restrict__ p, float* __restrict__ out)
{
    const size_t row0 = (size_t)blockIdx.x * 4;   // b*N + i0
    const int b = (int)(row0 >> 10);
    const int i0 = (int)(row0 & 1023);
    const int j4 = threadIdx.x;

    // independent loads first: the 256MB L stream + p broadcast
    float4 l[4];
#pragma unroll
    for (int r = 0; r < 4; r++)
        l[r] = __ldcs(reinterpret_cast<const float4*>(L) + (row0 + r) * 256 + j4);
    const float4 pj = __ldg(reinterpret_cast<const float4*>(p) + (size_t)b * 256 + j4);

#if __CUDA_ARCH__ >= 900
    cudaGridDependencySynchronize();
#endif

    float wi[4];
#pragma unroll
    for (int r = 0; r < 4; r++) wi[r] = __ldg(w + row0 + r);
    const float4 wj = __ldg(reinterpret_cast<const float4*>(w) + (size_t)b * 256 + j4);

#pragma unroll
    for (int r = 0; r < 4; r++) {
        float4 o;
        o.x = (1.f - wi[r] - wj.x) * l[r].x + wi[r] * pj.x;
        o.y = (1.f - wi[r] - wj.y) * l[r].y + wi[r] * pj.y;
        o.z = (1.f - wi[r] - wj.z) * l[r].z + wi[r] * pj.z;
        o.w = (1.f - wi[r] - wj.w) * l[r].w + wi[r] * pj.w;

        const int i = i0 + r;
        if (j4 == (i >> 2)) ((float*)&o)[i & 3] = 0.f;

        __stcs(reinterpret_cast<float4*>(out) + (row0 + r) * 256 + j4, o);
    }
}

static inline void launch_pdl(void* fn, dim3 grid, dim3 block, void** args,
                              cudaStream_t stream)
{
    cudaLaunchAttribute attr[1];
    attr[0].id = cudaLaunchAttributeProgrammaticStreamSerialization;
    attr[0].val.programmaticStreamSerializationAllowed = 1;

    cudaLaunchConfig_t cfg = {};
    cfg.gridDim = grid;
    cfg.blockDim = block;
    cfg.dynamicSmemBytes = 0;
    cfg.stream = stream;
    cfg.attrs = attr;
    cfg.numAttrs = 1;
    cudaLaunchKernelExC(&cfg, fn, args);
}

extern "C" void kernel_launch(void* const* d_in, const int* in_sizes, int n_in,
                              void* d_out, int out_size)
{
    const float* w_key  = (const float*)d_in[0];
    const float* w_beta = (const float*)d_in[1];
    // d_in[2] = e_vector (unused), d_in[3] = w_vector (unused)
    const float* a_gate = (const float*)d_in[4];
    const float* w_gate = (const float*)d_in[5];
    const float* alloc  = (const float*)d_in[6];
    const float* memory = (const float*)d_in[7];
    const float* linkm  = (const float*)d_in[8];
    const float* prec   = (const float*)d_in[9];

    float* out = (float*)d_out;
    float* out_w    = out;                                   // B*N
    float* out_mem  = out + (size_t)BB * NN;                 // B*N*W
    float* out_link = out_mem + (size_t)BB * NN * WW;        // B*N*N
    float* out_prec = out_link + (size_t)BB * NN * NN;       // B*N

    cudaStream_t s = 0;  // default (capture) stream

    wh_sim_kernel<<<BB * NN / 32, 256, 0, s>>>(w_key, w_beta, memory, out_mem);

    {
        void* args[] = { (void*)&a_gate, (void*)&w_gate, (void*)&alloc,
                         (void*)&prec, (void*)&out_w, (void*)&out_prec };
        launch_pdl((void*)wh_weights_kernel, dim3(BB), dim3(256), args, s);
    }
    {
        void* args[] = { (void*)&linkm, (void*)&out_w, (void*)&prec,
                         (void*)&out_link };
        launch_pdl((void*)wh_link_kernel, dim3(BB * NN / 4), dim3(256), args, s);
    }
}

// round 8
// speedup vs baseline: 1.0751x; 1.0751x over previous
#include <cuda_runtime.h>
#include <math.h>

#define EPSF 1e-8f
#define BB 64
#define NN 1024
#define WW 128

__device__ float g_sim[BB * NN];   // scratch: similarity logits

__device__ __forceinline__ float warp_sum(float v) {
#pragma unroll
    for (int o = 16; o; o >>= 1) v += __shfl_xor_sync(0xffffffffu, v, o);
    return v;
}
__device__ __forceinline__ float warp_max(float v) {
#pragma unroll
    for (int o = 16; o; o >>= 1) v = fmaxf(v, __shfl_xor_sync(0xffffffffu, v, o));
    return v;
}

// Phase 1: cosine similarity * beta + fused memory passthrough.
// 4 rows/warp, 8 warps/block, grid = B*N/32 = 2048 blocks. No smem, no sync.
__global__ __launch_bounds__(256) void wh_sim_kernel(
    const float* __restrict__ w_key, const float* __restrict__ w_beta,
    const float* __restrict__ memory, float* __restrict__ out_mem)
{
    const int t = threadIdx.x;
    const int lane = t & 31;
    const int warp = t >> 5;
    const size_t row0 = ((size_t)blockIdx.x * 8 + warp) * 4;  // first of 4 rows
    const int b = (int)(row0 >> 10);

    // each lane holds its 4 key components; norm via warp reduction
    const float4 k4 = __ldg(reinterpret_cast<const float4*>(w_key + b * WW) + lane);
    float ks = k4.x * k4.x + k4.y * k4.y + k4.z * k4.z + k4.w * k4.w;
    ks = warp_sum(ks);
    const float knorm = sqrtf(ks) + EPSF;

    const float bx = __ldg(w_beta + b);
    const float beta = 1.f + (bx > 20.f ? bx : log1pf(expf(bx)));

    float4 m[4];
#pragma unroll
    for (int r = 0; r < 4; r++)
        m[r] = reinterpret_cast<const float4*>(memory + (row0 + r) * WW)[lane];

    // fused passthrough copy (issued early; stores retire independently)
#pragma unroll
    for (int r = 0; r < 4; r++)
        __stcs(reinterpret_cast<float4*>(out_mem + (row0 + r) * WW) + lane, m[r]);

    float dot[4], sq[4];
#pragma unroll
    for (int r = 0; r < 4; r++) {
        dot[r] = m[r].x * k4.x + m[r].y * k4.y + m[r].z * k4.z + m[r].w * k4.w;
        sq[r]  = m[r].x * m[r].x + m[r].y * m[r].y + m[r].z * m[r].z + m[r].w * m[r].w;
    }
#pragma unroll
    for (int o = 16; o; o >>= 1) {
#pragma unroll
        for (int r = 0; r < 4; r++) {
            dot[r] += __shfl_xor_sync(0xffffffffu, dot[r], o);
            sq[r]  += __shfl_xor_sync(0xffffffffu, sq[r], o);
        }
    }
    if (lane == 0) {
#pragma unroll
        for (int r = 0; r < 4; r++)
            g_sim[row0 + r] = beta * dot[r] / ((sqrtf(sq[r]) + EPSF) * knorm);
    }
}

// Phase 2: softmax over N, gated write weights, precedence. One block per batch.
// PDL: loads independent inputs before grid-dep sync; triggers after out_w.
__global__ __launch_bounds__(256) void wh_weights_kernel(
    const float* __restrict__ a_gate, const float* __restrict__ w_gate,
    const float* __restrict__ alloc, const float* __restrict__ prec,
    float* __restrict__ out_w, float* __restrict__ out_prec)
{
    const int b = blockIdx.x;
    const int t = threadIdx.x;
    const int lane = t & 31;
    const int warp = t >> 5;

    __shared__ float s_red[8];

    const float wg = 1.f / (1.f + expf(-w_gate[b]));
    const float ag = 1.f / (1.f + expf(-a_gate[b]));
    float av[4], pv[4];
#pragma unroll
    for (int r = 0; r < 4; r++) {
        av[r] = alloc[(size_t)b * NN + t + r * 256];
        pv[r] = prec[(size_t)b * NN + t + r * 256];
    }

#if __CUDA_ARCH__ >= 900
    cudaGridDependencySynchronize();
#endif

    float sv[4];
    float mx = -INFINITY;
#pragma unroll
    for (int r = 0; r < 4; r++) {
        sv[r] = g_sim[(size_t)b * NN + t + r * 256];
        mx = fmaxf(mx, sv[r]);
    }
    mx = warp_max(mx);
    if (lane == 0) s_red[warp] = mx;
    __syncthreads();
    mx = s_red[0];
#pragma unroll
    for (int i = 1; i < 8; i++) mx = fmaxf(mx, s_red[i]);

    float ev[4];
    float esum = 0.f;
#pragma unroll
    for (int r = 0; r < 4; r++) {
        float e = expf(sv[r] - mx);
        ev[r] = e;
        esum += e;
    }
    __syncthreads();
    esum = warp_sum(esum);
    if (lane == 0) s_red[warp] = esum;
    __syncthreads();
    float ssum = s_red[0];
#pragma unroll
    for (int i = 1; i < 8; i++) ssum += s_red[i];
    const float inv = 1.f / ssum;

    float wv[4];
    float wsum = 0.f;
#pragma unroll
    for (int r = 0; r < 4; r++) {
        const int n = t + r * 256;
        const float c = ev[r] * inv;
        const float w = wg * (ag * av[r] + (1.f - ag) * c);
        wv[r] = w;
        wsum += w;
        out_w[(size_t)b * NN + n] = w;
    }

#if __CUDA_ARCH__ >= 900
    cudaTriggerProgrammaticLaunchCompletion();
#endif

    __syncthreads();
    wsum = warp_sum(wsum);
    if (lane == 0) s_red[warp] = wsum;
    __syncthreads();
    float tot = s_red[0];
#pragma unroll
    for (int i = 1; i < 8; i++) tot += s_red[i];

#pragma unroll
    for (int r = 0; r < 4; r++) {
        const int n = t + r * 256;
        out_prec[(size_t)b * NN + n] = (1.f - tot) * pv[r] + wv[r];
    }
}

// Link update: 4 rows per block. PDL: L/p loads before grid-dep sync, w after.
// link = (1 - wi - wj)*L + wi*pj; diag = 0.
__global__ __launch_bounds__(256) void wh_link_kernel(
    const float* __restrict__ L, const float* __restrict__ w,
    const float* __restrict__ p, float* __restrict__ out)
{
    const size_t row0 = (size_t)blockIdx.x * 4;   // b*N + i0
    const int b = (int)(row0 >> 10);
    const int i0 = (int)(row0 & 1023);
    const int j4 = threadIdx.x;

    float4 l[4];
#pragma unroll
    for (int r = 0; r < 4; r++)
        l[r] = __ldcs(reinterpret_cast<const float4*>(L) + (row0 + r) * 256 + j4);
    const float4 pj = __ldg(reinterpret_cast<const float4*>(p) + (size_t)b * 256 + j4);

#if __CUDA_ARCH__ >= 900
    cudaGridDependencySynchronize();
#endif

    float wi[4];
#pragma unroll
    for (int r = 0; r < 4; r++) wi[r] = __ldg(w + row0 + r);
    const float4 wj = __ldg(reinterpret_cast<const float4*>(w) + (size_t)b * 256 + j4);

#pragma unroll
    for (int r = 0; r < 4; r++) {
        float4 o;
        o.x = (1.f - wi[r] - wj.x) * l[r].x + wi[r] * pj.x;
        o.y = (1.f - wi[r] - wj.y) * l[r].y + wi[r] * pj.y;
        o.z = (1.f - wi[r] - wj.z) * l[r].z + wi[r] * pj.z;
        o.w = (1.f - wi[r] - wj.w) * l[r].w + wi[r] * pj.w;

        const int i = i0 + r;
        if (j4 == (i >> 2)) ((float*)&o)[i & 3] = 0.f;

        __stcs(reinterpret_cast<float4*>(out) + (row0 + r) * 256 + j4, o);
    }
}

static inline void launch_pdl(void* fn, dim3 grid, dim3 block, void** args,
                              cudaStream_t stream)
{
    cudaLaunchAttribute attr[1];
    attr[0].id = cudaLaunchAttributeProgrammaticStreamSerialization;
    attr[0].val.programmaticStreamSerializationAllowed = 1;

    cudaLaunchConfig_t cfg = {};
    cfg.gridDim = grid;
    cfg.blockDim = block;
    cfg.dynamicSmemBytes = 0;
    cfg.stream = stream;
    cfg.attrs = attr;
    cfg.numAttrs = 1;
    cudaLaunchKernelExC(&cfg, fn, args);
}

extern "C" void kernel_launch(void* const* d_in, const int* in_sizes, int n_in,
                              void* d_out, int out_size)
{
    const float* w_key  = (const float*)d_in[0];
    const float* w_beta = (const float*)d_in[1];
    // d_in[2] = e_vector (unused), d_in[3] = w_vector (unused)
    const float* a_gate = (const float*)d_in[4];
    const float* w_gate = (const float*)d_in[5];
    const float* alloc  = (const float*)d_in[6];
    const float* memory = (const float*)d_in[7];
    const float* linkm  = (const float*)d_in[8];
    const float* prec   = (const float*)d_in[9];

    float* out = (float*)d_out;
    float* out_w    = out;                                   // B*N
    float* out_mem  = out + (size_t)BB * NN;                 // B*N*W
    float* out_link = out_mem + (size_t)BB * NN * WW;        // B*N*N
    float* out_prec = out_link + (size_t)BB * NN * NN;       // B*N

    cudaStream_t s = 0;

    // plain launch: sim kernel stays register-lean
    wh_sim_kernel<<<BB * NN / 32, 256, 0, s>>>(w_key, w_beta, memory, out_mem);

    {
        void* args[] = { (void*)&a_gate, (void*)&w_gate, (void*)&alloc,
                         (void*)&prec, (void*)&out_w, (void*)&out_prec };
        launch_pdl((void*)wh_weights_kernel, dim3(BB), dim3(256), args, s);
    }
    {
        void* args[] = { (void*)&linkm, (void*)&out_w, (void*)&prec,
                         (void*)&out_link };
        launch_pdl((void*)wh_link_kernel, dim3(BB * NN / 4), dim3(256), args, s);
    }
}

// round 9
// speedup vs baseline: 1.0880x; 1.0120x over previous
#include <cuda_runtime.h>
#include <math.h>

#define EPSF 1e-8f
#define BB 64
#define NN 1024
#define WW 128

__device__ float g_sim[BB * NN];   // scratch: similarity logits

__device__ __forceinline__ float warp_sum(float v) {
#pragma unroll
    for (int o = 16; o; o >>= 1) v += __shfl_xor_sync(0xffffffffu, v, o);
    return v;
}
__device__ __forceinline__ float warp_max(float v) {
#pragma unroll
    for (int o = 16; o; o >>= 1) v = fmaxf(v, __shfl_xor_sync(0xffffffffu, v, o));
    return v;
}

// Phase 1: cosine similarity * beta + fused memory passthrough.
// 4 rows/warp, 8 warps/block, grid = 2048. Tree-merge reduction: 17 SHFLs
// for 8 values instead of 40 (two full butterflies).
__global__ __launch_bounds__(256) void wh_sim_kernel(
    const float* __restrict__ w_key, const float* __restrict__ w_beta,
    const float* __restrict__ memory, float* __restrict__ out_mem)
{
    const int t = threadIdx.x;
    const int lane = t & 31;
    const int warp = t >> 5;
    const size_t row0 = ((size_t)blockIdx.x * 8 + warp) * 4;  // first of 4 rows
    const int b = (int)(row0 >> 10);
    const unsigned FULL = 0xffffffffu;

    // each lane holds its 4 key components; norm via warp reduction
    const float4 k4 = __ldg(reinterpret_cast<const float4*>(w_key + b * WW) + lane);
    float ks = k4.x * k4.x + k4.y * k4.y + k4.z * k4.z + k4.w * k4.w;
    ks = warp_sum(ks);
    const float knorm = sqrtf(ks) + EPSF;

    const float bx = __ldg(w_beta + b);
    const float beta = 1.f + (bx > 20.f ? bx : log1pf(expf(bx)));

    float4 m[4];
#pragma unroll
    for (int r = 0; r < 4; r++)
        m[r] = reinterpret_cast<const float4*>(memory + (row0 + r) * WW)[lane];

    // fused passthrough copy (stores retire independently)
#pragma unroll
    for (int r = 0; r < 4; r++)
        __stcs(reinterpret_cast<float4*>(out_mem + (row0 + r) * WW) + lane, m[r]);

    float dot[4], sq[4];
#pragma unroll
    for (int r = 0; r < 4; r++) {
        dot[r] = m[r].x * k4.x + m[r].y * k4.y + m[r].z * k4.z + m[r].w * k4.w;
        sq[r]  = m[r].x * m[r].x + m[r].y * m[r].y + m[r].z * m[r].z + m[r].w * m[r].w;
    }

    // ---- tree-merge reduction: 8 values -> lane-indexed sums ----
    // level 1 (off 16): A[r] holds dot_r partial in lanes<16, sq_r in lanes>=16
    const bool lo16 = (lane & 16) == 0;
    float A[4];
#pragma unroll
    for (int r = 0; r < 4; r++) {
        float dx = __shfl_xor_sync(FULL, dot[r], 16);
        float sx = __shfl_xor_sync(FULL, sq[r], 16);
        A[r] = lo16 ? (dot[r] + dx) : (sq[r] + sx);
    }
    // level 2 (off 8): B0 <- {A0,A1}, B1 <- {A2,A3}
    const bool lo8 = (lane & 8) == 0;
    float a0 = __shfl_xor_sync(FULL, A[0], 8);
    float a1 = __shfl_xor_sync(FULL, A[1], 8);
    float B0 = lo8 ? (A[0] + a0) : (A[1] + a1);
    float a2 = __shfl_xor_sync(FULL, A[2], 8);
    float a3 = __shfl_xor_sync(FULL, A[3], 8);
    float B1 = lo8 ? (A[2] + a2) : (A[3] + a3);
    // level 3 (off 4): C <- {B0,B1}
    const bool lo4 = (lane & 4) == 0;
    float b0 = __shfl_xor_sync(FULL, B0, 4);
    float b1 = __shfl_xor_sync(FULL, B1, 4);
    float C = lo4 ? (B0 + b0) : (B1 + b1);
    // finish within 4-lane groups (value selection independent of bits 0,1)
    C += __shfl_xor_sync(FULL, C, 2);
    C += __shfl_xor_sync(FULL, C, 1);
    // pair dot_r (lanes<16) with sq_r (lanes>=16)
    const float sqv = __shfl_xor_sync(FULL, C, 16);

    // lanes 0,4,8,12 hold dot for r = ((lane&4)?2:0) + ((lane&8)?1:0)
    if ((lane & 19) == 0) {
        const int r = ((lane & 4) ? 2 : 0) + ((lane & 8) ? 1 : 0);
        g_sim[row0 + r] = beta * C / ((sqrtf(sqv) + EPSF) * knorm);
    }
}

// Phase 2: softmax over N, gated write weights, precedence. One block per batch.
// PDL: loads independent inputs before grid-dep sync; triggers after out_w.
__global__ __launch_bounds__(256) void wh_weights_kernel(
    const float* __restrict__ a_gate, const float* __restrict__ w_gate,
    const float* __restrict__ alloc, const float* __restrict__ prec,
    float* __restrict__ out_w, float* __restrict__ out_prec)
{
    const int b = blockIdx.x;
    const int t = threadIdx.x;
    const int lane = t & 31;
    const int warp = t >> 5;

    __shared__ float s_red[8];

    const float wg = 1.f / (1.f + expf(-w_gate[b]));
    const float ag = 1.f / (1.f + expf(-a_gate[b]));
    float av[4], pv[4];
#pragma unroll
    for (int r = 0; r < 4; r++) {
        av[r] = alloc[(size_t)b * NN + t + r * 256];
        pv[r] = prec[(size_t)b * NN + t + r * 256];
    }

#if __CUDA_ARCH__ >= 900
    cudaGridDependencySynchronize();
#endif

    float sv[4];
    float mx = -INFINITY;
#pragma unroll
    for (int r = 0; r < 4; r++) {
        sv[r] = g_sim[(size_t)b * NN + t + r * 256];
        mx = fmaxf(mx, sv[r]);
    }
    mx = warp_max(mx);
    if (lane == 0) s_red[warp] = mx;
    __syncthreads();
    mx = s_red[0];
#pragma unroll
    for (int i = 1; i < 8; i++) mx = fmaxf(mx, s_red[i]);

    float ev[4];
    float esum = 0.f;
#pragma unroll
    for (int r = 0; r < 4; r++) {
        float e = expf(sv[r] - mx);
        ev[r] = e;
        esum += e;
    }
    __syncthreads();
    esum = warp_sum(esum);
    if (lane == 0) s_red[warp] = esum;
    __syncthreads();
    float ssum = s_red[0];
#pragma unroll
    for (int i = 1; i < 8; i++) ssum += s_red[i];
    const float inv = 1.f / ssum;

    float wv[4];
    float wsum = 0.f;
#pragma unroll
    for (int r = 0; r < 4; r++) {
        const int n = t + r * 256;
        const float c = ev[r] * inv;
        const float w = wg * (ag * av[r] + (1.f - ag) * c);
        wv[r] = w;
        wsum += w;
        out_w[(size_t)b * NN + n] = w;
    }

#if __CUDA_ARCH__ >= 900
    cudaTriggerProgrammaticLaunchCompletion();
#endif

    __syncthreads();
    wsum = warp_sum(wsum);
    if (lane == 0) s_red[warp] = wsum;
    __syncthreads();
    float tot = s_red[0];
#pragma unroll
    for (int i = 1; i < 8; i++) tot += s_red[i];

#pragma unroll
    for (int r = 0; r < 4; r++) {
        const int n = t + r * 256;
        out_prec[(size_t)b * NN + n] = (1.f - tot) * pv[r] + wv[r];
    }
}

// Link update: 4 rows per block. PDL: L/p loads before grid-dep sync, w after.
// link = (1 - wi - wj)*L + wi*pj; diag = 0.
__global__ __launch_bounds__(256) void wh_link_kernel(
    const float* __restrict__ L, const float* __restrict__ w,
    const float* __restrict__ p, float* __restrict__ out)
{
    const size_t row0 = (size_t)blockIdx.x * 4;   // b*N + i0
    const int b = (int)(row0 >> 10);
    const int i0 = (int)(row0 & 1023);
    const int j4 = threadIdx.x;

    float4 l[4];
#pragma unroll
    for (int r = 0; r < 4; r++)
        l[r] = __ldcs(reinterpret_cast<const float4*>(L) + (row0 + r) * 256 + j4);
    const float4 pj = __ldg(reinterpret_cast<const float4*>(p) + (size_t)b * 256 + j4);

#if __CUDA_ARCH__ >= 900
    cudaGridDependencySynchronize();
#endif

    float wi[4];
#pragma unroll
    for (int r = 0; r < 4; r++) wi[r] = __ldg(w + row0 + r);
    const float4 wj = __ldg(reinterpret_cast<const float4*>(w) + (size_t)b * 256 + j4);

#pragma unroll
    for (int r = 0; r < 4; r++) {
        float4 o;
        o.x = (1.f - wi[r] - wj.x) * l[r].x + wi[r] * pj.x;
        o.y = (1.f - wi[r] - wj.y) * l[r].y + wi[r] * pj.y;
        o.z = (1.f - wi[r] - wj.z) * l[r].z + wi[r] * pj.z;
        o.w = (1.f - wi[r] - wj.w) * l[r].w + wi[r] * pj.w;

        const int i = i0 + r;
        if (j4 == (i >> 2)) ((float*)&o)[i & 3] = 0.f;

        __stcs(reinterpret_cast<float4*>(out) + (row0 + r) * 256 + j4, o);
    }
}

static inline void launch_pdl(void* fn, dim3 grid, dim3 block, void** args,
                              cudaStream_t stream)
{
    cudaLaunchAttribute attr[1];
    attr[0].id = cudaLaunchAttributeProgrammaticStreamSerialization;
    attr[0].val.programmaticStreamSerializationAllowed = 1;

    cudaLaunchConfig_t cfg = {};
    cfg.gridDim = grid;
    cfg.blockDim = block;
    cfg.dynamicSmemBytes = 0;
    cfg.stream = stream;
    cfg.attrs = attr;
    cfg.numAttrs = 1;
    cudaLaunchKernelExC(&cfg, fn, args);
}

extern "C" void kernel_launch(void* const* d_in, const int* in_sizes, int n_in,
                              void* d_out, int out_size)
{
    const float* w_key  = (const float*)d_in[0];
    const float* w_beta = (const float*)d_in[1];
    // d_in[2] = e_vector (unused), d_in[3] = w_vector (unused)
    const float* a_gate = (const float*)d_in[4];
    const float* w_gate = (const float*)d_in[5];
    const float* alloc  = (const float*)d_in[6];
    const float* memory = (const float*)d_in[7];
    const float* linkm  = (const float*)d_in[8];
    const float* prec   = (const float*)d_in[9];

    float* out = (float*)d_out;
    float* out_w    = out;                                   // B*N
    float* out_mem  = out + (size_t)BB * NN;                 // B*N*W
    float* out_link = out_mem + (size_t)BB * NN * WW;        // B*N*N
    float* out_prec = out_link + (size_t)BB * NN * NN;       // B*N

    cudaStream_t s = 0;

    wh_sim_kernel<<<BB * NN / 32, 256, 0, s>>>(w_key, w_beta, memory, out_mem);

    {
        void* args[] = { (void*)&a_gate, (void*)&w_gate, (void*)&alloc,
                         (void*)&prec, (void*)&out_w, (void*)&out_prec };
        launch_pdl((void*)wh_weights_kernel, dim3(BB), dim3(256), args, s);
    }
    {
        void* args[] = { (void*)&linkm, (void*)&out_w, (void*)&prec,
                         (void*)&out_link };
        launch_pdl((void*)wh_link_kernel, dim3(BB * NN / 4), dim3(256), args, s);
    }
}

// round 10
// speedup vs baseline: 1.0978x; 1.0090x over previous
#include <cuda_runtime.h>
#include <math.h>

#define EPSF 1e-8f
#define BB 64
#define NN 1024
#define WW 128

__device__ float  g_e[BB * NN];    // scratch: exp(beta * cosine)
__device__ float4 g_scal[BB];      // per-batch {wg*ag, wg*(1-ag)/esum, 1-wsum, 0}

__device__ __forceinline__ float warp_sum(float v) {
#pragma unroll
    for (int o = 16; o; o >>= 1) v += __shfl_xor_sync(0xffffffffu, v, o);
    return v;
}

// Phase 1: e = exp(beta * cosine) + fused memory passthrough.
// 4 rows/warp, 8 warps/block, grid = 2048. Tree-merge reduction (17 SHFLs).
__global__ __launch_bounds__(256) void wh_sim_kernel(
    const float* __restrict__ w_key, const float* __restrict__ w_beta,
    const float* __restrict__ memory, float* __restrict__ out_mem)
{
    const int t = threadIdx.x;
    const int lane = t & 31;
    const int warp = t >> 5;
    const size_t row0 = ((size_t)blockIdx.x * 8 + warp) * 4;  // first of 4 rows
    const int b = (int)(row0 >> 10);
    const unsigned FULL = 0xffffffffu;

    const float4 k4 = __ldg(reinterpret_cast<const float4*>(w_key + b * WW) + lane);
    float ks = k4.x * k4.x + k4.y * k4.y + k4.z * k4.z + k4.w * k4.w;
    ks = warp_sum(ks);
    const float knorm = sqrtf(ks) + EPSF;

    const float bx = __ldg(w_beta + b);
    const float beta = 1.f + (bx > 20.f ? bx : log1pf(expf(bx)));

    float4 m[4];
#pragma unroll
    for (int r = 0; r < 4; r++)
        m[r] = reinterpret_cast<const float4*>(memory + (row0 + r) * WW)[lane];

    // fused passthrough copy (stores retire independently)
#pragma unroll
    for (int r = 0; r < 4; r++)
        __stcs(reinterpret_cast<float4*>(out_mem + (row0 + r) * WW) + lane, m[r]);

    float dot[4], sq[4];
#pragma unroll
    for (int r = 0; r < 4; r++) {
        dot[r] = m[r].x * k4.x + m[r].y * k4.y + m[r].z * k4.z + m[r].w * k4.w;
        sq[r]  = m[r].x * m[r].x + m[r].y * m[r].y + m[r].z * m[r].z + m[r].w * m[r].w;
    }

    // ---- tree-merge reduction: 8 values -> lane-indexed sums ----
    const bool lo16 = (lane & 16) == 0;
    float A[4];
#pragma unroll
    for (int r = 0; r < 4; r++) {
        float dx = __shfl_xor_sync(FULL, dot[r], 16);
        float sx = __shfl_xor_sync(FULL, sq[r], 16);
        A[r] = lo16 ? (dot[r] + dx) : (sq[r] + sx);
    }
    const bool lo8 = (lane & 8) == 0;
    float a0 = __shfl_xor_sync(FULL, A[0], 8);
    float a1 = __shfl_xor_sync(FULL, A[1], 8);
    float B0 = lo8 ? (A[0] + a0) : (A[1] + a1);
    float a2 = __shfl_xor_sync(FULL, A[2], 8);
    float a3 = __shfl_xor_sync(FULL, A[3], 8);
    float B1 = lo8 ? (A[2] + a2) : (A[3] + a3);
    const bool lo4 = (lane & 4) == 0;
    float b0 = __shfl_xor_sync(FULL, B0, 4);
    float b1 = __shfl_xor_sync(FULL, B1, 4);
    float C = lo4 ? (B0 + b0) : (B1 + b1);
    C += __shfl_xor_sync(FULL, C, 2);
    C += __shfl_xor_sync(FULL, C, 1);
    const float sqv = __shfl_xor_sync(FULL, C, 16);

    // lanes 0,4,8,12 hold dot for r = ((lane&4)?2:0) + ((lane&8)?1:0)
    if ((lane & 19) == 0) {
        const int r = ((lane & 4) ? 2 : 0) + ((lane & 8) ? 1 : 0);
        const float sim = beta * C / ((sqrtf(sqv) + EPSF) * knorm);
        g_e[row0 + r] = expf(sim);   // no-max softmax numerator (|sim| small)
    }
}

// Phase 2: per-batch scalar reduction. 64 blocks x 256 threads.
// Emits {wg*ag, wg*(1-ag)/esum, 1 - wsum} with wsum = wg*(ag*S_alloc + (1-ag)).
__global__ __launch_bounds__(256) void wh_scal_kernel(
    const float* __restrict__ a_gate, const float* __restrict__ w_gate,
    const float* __restrict__ alloc)
{
    const int b = blockIdx.x;
    const int t = threadIdx.x;
    const int lane = t & 31;
    const int warp = t >> 5;
    __shared__ float s_e[8], s_a[8];

    // independent inputs before grid-dep sync
    const float wg = 1.f / (1.f + expf(-w_gate[b]));
    const float ag = 1.f / (1.f + expf(-a_gate[b]));
    const float4 av = __ldg(reinterpret_cast<const float4*>(alloc + (size_t)b * NN) + t);
    float sa = av.x + av.y + av.z + av.w;

#if __CUDA_ARCH__ >= 900
    cudaGridDependencySynchronize();
#endif

    const float4 e4 = *(reinterpret_cast<const float4*>(g_e + (size_t)b * NN) + t);
    float se = e4.x + e4.y + e4.z + e4.w;

    se = warp_sum(se);
    sa = warp_sum(sa);
    if (lane == 0) { s_e[warp] = se; s_a[warp] = sa; }
    __syncthreads();
    if (t == 0) {
        float esum = 0.f, asum = 0.f;
#pragma unroll
        for (int i = 0; i < 8; i++) { esum += s_e[i]; asum += s_a[i]; }
        const float s0 = wg * ag;                       // alloc coefficient
        const float s1 = wg * (1.f - ag) / esum;        // e coefficient
        const float wsum = wg * (ag * asum + (1.f - ag));
        g_scal[b] = make_float4(s0, s1, 1.f - wsum, 0.f);
    }
}

// Phase 3: link update with on-the-fly w. 4 rows/block.
// w_j = s0*alloc_j + s1*e_j ; link = (1-wi-wj)*L + wi*pj ; diag=0.
// Blocks with i0==0 additionally write out_w[b,:] and out_prec[b,:].
__global__ __launch_bounds__(256) void wh_link_kernel(
    const float* __restrict__ L, const float* __restrict__ alloc,
    const float* __restrict__ p, float* __restrict__ out,
    float* __restrict__ out_w, float* __restrict__ out_prec)
{
    const size_t row0 = (size_t)blockIdx.x * 4;   // b*N + i0
    const int b = (int)(row0 >> 10);
    const int i0 = (int)(row0 & 1023);
    const int j4 = threadIdx.x;

    // independent loads first: 256MB L stream + p + alloc broadcasts
    float4 l[4];
#pragma unroll
    for (int r = 0; r < 4; r++)
        l[r] = __ldcs(reinterpret_cast<const float4*>(L) + (row0 + r) * 256 + j4);
    const float4 pj = __ldg(reinterpret_cast<const float4*>(p) + (size_t)b * 256 + j4);
    const float4 aj = __ldg(reinterpret_cast<const float4*>(alloc) + (size_t)b * 256 + j4);
    float ai[4];
#pragma unroll
    for (int r = 0; r < 4; r++) ai[r] = __ldg(alloc + row0 + r);

#if __CUDA_ARCH__ >= 900
    cudaGridDependencySynchronize();
#endif

    const float4 sc = g_scal[b];      // {s0, s1, 1-wsum, _}
    const float4 ej = *(reinterpret_cast<const float4*>(g_e + (size_t)b * NN) + j4);

    float4 wj;
    wj.x = sc.x * aj.x + sc.y * ej.x;
    wj.y = sc.x * aj.y + sc.y * ej.y;
    wj.z = sc.x * aj.z + sc.y * ej.z;
    wj.w = sc.x * aj.w + sc.y * ej.w;

    float wi[4];
#pragma unroll
    for (int r = 0; r < 4; r++)
        wi[r] = sc.x * ai[r] + sc.y * g_e[row0 + r];

#pragma unroll
    for (int r = 0; r < 4; r++) {
        float4 o;
        o.x = (1.f - wi[r] - wj.x) * l[r].x + wi[r] * pj.x;
        o.y = (1.f - wi[r] - wj.y) * l[r].y + wi[r] * pj.y;
        o.z = (1.f - wi[r] - wj.z) * l[r].z + wi[r] * pj.z;
        o.w = (1.f - wi[r] - wj.w) * l[r].w + wi[r] * pj.w;

        const int i = i0 + r;
        if (j4 == (i >> 2)) ((float*)&o)[i & 3] = 0.f;

        __stcs(reinterpret_cast<float4*>(out) + (row0 + r) * 256 + j4, o);
    }

    // one block per batch emits w_weights and precedence_new
    if (i0 == 0) {
        reinterpret_cast<float4*>(out_w + (size_t)b * NN)[j4] = wj;
        float4 pn;
        pn.x = sc.z * pj.x + wj.x;
        pn.y = sc.z * pj.y + wj.y;
        pn.z = sc.z * pj.z + wj.z;
        pn.w = sc.z * pj.w + wj.w;
        reinterpret_cast<float4*>(out_prec + (size_t)b * NN)[j4] = pn;
    }
}

static inline void launch_pdl(void* fn, dim3 grid, dim3 block, void** args,
                              cudaStream_t stream)
{
    cudaLaunchAttribute attr[1];
    attr[0].id = cudaLaunchAttributeProgrammaticStreamSerialization;
    attr[0].val.programmaticStreamSerializationAllowed = 1;

    cudaLaunchConfig_t cfg = {};
    cfg.gridDim = grid;
    cfg.blockDim = block;
    cfg.dynamicSmemBytes = 0;
    cfg.stream = stream;
    cfg.attrs = attr;
    cfg.numAttrs = 1;
    cudaLaunchKernelExC(&cfg, fn, args);
}

extern "C" void kernel_launch(void* const* d_in, const int* in_sizes, int n_in,
                              void* d_out, int out_size)
{
    const float* w_key  = (const float*)d_in[0];
    const float* w_beta = (const float*)d_in[1];
    // d_in[2] = e_vector (unused), d_in[3] = w_vector (unused)
    const float* a_gate = (const float*)d_in[4];
    const float* w_gate = (const float*)d_in[5];
    const float* alloc  = (const float*)d_in[6];
    const float* memory = (const float*)d_in[7];
    const float* linkm  = (const float*)d_in[8];
    const float* prec   = (const float*)d_in[9];

    float* out = (float*)d_out;
    float* out_w    = out;                                   // B*N
    float* out_mem  = out + (size_t)BB * NN;                 // B*N*W
    float* out_link = out_mem + (size_t)BB * NN * WW;        // B*N*N
    float* out_prec = out_link + (size_t)BB * NN * NN;       // B*N

    cudaStream_t s = 0;

    wh_sim_kernel<<<BB * NN / 32, 256, 0, s>>>(w_key, w_beta, memory, out_mem);

    {
        void* args[] = { (void*)&a_gate, (void*)&w_gate, (void*)&alloc };
        launch_pdl((void*)wh_scal_kernel, dim3(BB), dim3(256), args, s);
    }
    {
        void* args[] = { (void*)&linkm, (void*)&alloc, (void*)&prec,
                         (void*)&out_link, (void*)&out_w, (void*)&out_prec };
        launch_pdl((void*)wh_link_kernel, dim3(BB * NN / 4), dim3(256), args, s);
    }
}